// round 17
// baseline (speedup 1.0000x reference)
#include <cuda_runtime.h>

// Poolpointsinterp R13: spatially sorted points + direct NCHW fp32 gather.
// No transpose, no scratch. Sorted order makes the per-channel 32B sectors
// (feat[c][y][x..x+7]) reusable in L1 across the points of a block.

#define SPATIAL_SCALE 0.25f
#define Nn 8
#define Cc 256
#define Hh 128
#define Ww 128
#define HW (Hh * Ww)

#define NBINS 8192            // 8 (b) x 32 (y/4) x 32 (x/4)
#define PTS_PER_WARP 8
#define PTS_PER_BLOCK 64      // 8 warps x 8 points

__device__ int g_hist[NBINS];
__device__ int g_cursor[NBINS];
__device__ int g_perm[1 << 17];

// ---------------------------------------------------------------------------
__device__ __forceinline__ int bin_of(const float* __restrict__ rois, int p)
{
    int b = (int)rois[p * 3 + 0];
    float x = fmaxf(rois[p * 3 + 1] * SPATIAL_SCALE, 0.0f);
    float y = fmaxf(rois[p * 3 + 2] * SPATIAL_SCALE, 0.0f);
    int yl = min((int)floorf(y), Hh - 1);
    int xl = min((int)floorf(x), Ww - 1);
    return ((b << 5) + (yl >> 2)) * 32 + (xl >> 2);
}

__global__ void zero_kernel()
{
    int i = blockIdx.x * blockDim.x + threadIdx.x;
    if (i < NBINS) g_hist[i] = 0;
}

__global__ void __launch_bounds__(256) hist_kernel(const float* __restrict__ rois, int P)
{
    __shared__ int cnt[NBINS];      // 32 KB
    int tid = threadIdx.x;
    for (int i = tid; i < NBINS; i += 256) cnt[i] = 0;
    __syncthreads();
    int p = blockIdx.x * 256 + tid;
    if (p < P) atomicAdd(&cnt[bin_of(rois, p)], 1);
    __syncthreads();
    for (int i = tid; i < NBINS; i += 256)
        if (cnt[i]) atomicAdd(&g_hist[i], cnt[i]);
}

// Single-block exclusive scan over 8192 counters -> g_cursor.
__global__ void __launch_bounds__(1024) scan_kernel()
{
    __shared__ int warpsum[32];
    int tid = threadIdx.x, lane = tid & 31, wid = tid >> 5;

    int v[8], e[8], s = 0;
    #pragma unroll
    for (int j = 0; j < 8; j++) {
        v[j] = g_hist[tid * 8 + j];
        e[j] = s;
        s += v[j];
    }
    // warp inclusive scan of per-thread sums
    int inc = s;
    #pragma unroll
    for (int o = 1; o < 32; o <<= 1) {
        int n = __shfl_up_sync(0xFFFFFFFFu, inc, o);
        if (lane >= o) inc += n;
    }
    if (lane == 31) warpsum[wid] = inc;
    __syncthreads();
    if (wid == 0) {
        int w = warpsum[lane];
        int wi = w;
        #pragma unroll
        for (int o = 1; o < 32; o <<= 1) {
            int n = __shfl_up_sync(0xFFFFFFFFu, wi, o);
            if (lane >= o) wi += n;
        }
        warpsum[lane] = wi - w;      // exclusive warp base
    }
    __syncthreads();
    int base = warpsum[wid] + (inc - s);
    #pragma unroll
    for (int j = 0; j < 8; j++)
        g_cursor[tid * 8 + j] = base + e[j];
}

__global__ void __launch_bounds__(256) scatter_kernel(const float* __restrict__ rois, int P)
{
    __shared__ int cnt[NBINS];      // 32 KB, reused count -> base
    int tid = threadIdx.x;
    for (int i = tid; i < NBINS; i += 256) cnt[i] = 0;
    __syncthreads();
    int p = blockIdx.x * 256 + tid;
    int b = 0, rank = 0;
    bool has = (p < P);
    if (has) {
        b = bin_of(rois, p);
        rank = atomicAdd(&cnt[b], 1);
    }
    __syncthreads();
    for (int i = tid; i < NBINS; i += 256) {
        int c = cnt[i];
        if (c) cnt[i] = atomicAdd(&g_cursor[i], c);
    }
    __syncthreads();
    if (has) g_perm[cnt[b] + rank] = p;
}

// ---------------------------------------------------------------------------
// Gather: warp handles 8 consecutive sorted points; lane t covers channels
// 8t..8t+7. Per point: 32 independent scalar loads (L1-cached; repeats across
// the block's sorted points hit L1). Output: 2 x float4 streaming stores/lane.
// ---------------------------------------------------------------------------
__global__ void __launch_bounds__(256) gather_kernel(
    const float* __restrict__ feat,
    const float* __restrict__ rois,
    float* __restrict__ out,
    int P)
{
    int warp = threadIdx.x >> 5;
    int t    = threadIdx.x & 31;
    int pos0 = blockIdx.x * PTS_PER_BLOCK + warp * PTS_PER_WARP;

    #pragma unroll
    for (int k = 0; k < PTS_PER_WARP; k++) {
        int pos = pos0 + k;
        if (pos >= P) return;
        int p = g_perm[pos];

        float rb = rois[p * 3 + 0];
        float rx = rois[p * 3 + 1];
        float ry = rois[p * 3 + 2];
        int bi = (int)rb;
        float x = rx * SPATIAL_SCALE;
        float y = ry * SPATIAL_SCALE;

        bool valid = (y >= -1.0f) & (y <= (float)Hh) & (x >= -1.0f) & (x <= (float)Ww);

        y = fmaxf(y, 0.0f);
        x = fmaxf(x, 0.0f);
        int y_low = (int)floorf(y);
        int x_low = (int)floorf(x);
        int dX = 1, dys = 1;
        if (y_low >= Hh - 1) { y_low = Hh - 1; dys = 0; y = (float)y_low; }
        if (x_low >= Ww - 1) { x_low = Ww - 1; dX = 0;  x = (float)x_low; }
        int dY = dys * Ww;

        float ly = y - (float)y_low;
        float lx = x - (float)x_low;
        float hy = 1.0f - ly;
        float hx = 1.0f - lx;
        float w1 = hy * hx, w2 = hy * lx, w3 = ly * hx, w4 = ly * lx;

        // Lane base: batch bi, channel 8t, pixel (y_low, x_low).
        const float* f = feat + (size_t)bi * Cc * HW
                              + (size_t)(t * 8) * HW
                              + y_low * Ww + x_low;

        float o[8];
        #pragma unroll
        for (int i = 0; i < 8; i++) {
            const float* fc = f + i * HW;
            float v1 = fc[0];
            float v2 = fc[dX];
            float v3 = fc[dY];
            float v4 = fc[dY + dX];
            o[i] = w1 * v1 + w2 * v2 + w3 * v3 + w4 * v4;
        }
        if (!valid) {
            #pragma unroll
            for (int i = 0; i < 8; i++) o[i] = 0.0f;
        }

        float4* dst = (float4*)(out + (size_t)p * Cc + t * 8);
        __stcs(dst + 0, make_float4(o[0], o[1], o[2], o[3]));
        __stcs(dst + 1, make_float4(o[4], o[5], o[6], o[7]));
    }
}

extern "C" void kernel_launch(void* const* d_in, const int* in_sizes, int n_in,
                              void* d_out, int out_size)
{
    const float* feat = (const float*)d_in[0];
    const float* rois = (const float*)d_in[1];
    float* out = (float*)d_out;
    int P = in_sizes[1] / 3;

    zero_kernel<<<(NBINS + 1023) / 1024, 1024>>>();
    hist_kernel<<<(P + 255) / 256, 256>>>(rois, P);
    scan_kernel<<<1, 1024>>>();
    scatter_kernel<<<(P + 255) / 256, 256>>>(rois, P);

    gather_kernel<<<(P + PTS_PER_BLOCK - 1) / PTS_PER_BLOCK, 256>>>(feat, rois, out, P);
}